// round 11
// baseline (speedup 1.0000x reference)
#include <cuda_runtime.h>
#include <cuda_fp16.h>
#include <cstdint>
#include <math.h>

// ConvergedInhibition == circular deconvolution along C=128 channels.
// Y = G @ X, G[r][j] = g[(r-j)&127], g = ifft(1/fft(delta-k)).
// R11: R10 + DEPTH-2 cp.async prefetch (double-buffered fp32 staging,
//      wait_group 1): each tile's gmem loads get ~2 tile-iterations of
//      latency/queue cover. Single-pass fp16 mma, register A-frags via
//      circulant diagonal classes, coalesced STG.128 epilogue.
//      Tile = 128m x 64n. smem 87KB/CTA, 2 CTAs/SM.

#define CCH     128
#define HWSZ    4096
#define NBATCH  64
#define SCOPE   27
#define NTILE_N 64
#define NTHREADS 256
#define NTILES_TOTAL (NBATCH * (HWSZ / NTILE_N))   // 4096

#define SPITCH_B 272                    // staging row: 64 fp32 + 16B pad
#define STAGE_B  (CCH * SPITCH_B)       // 34816
#define SMEM_S0  0
#define SMEM_S1  STAGE_B
#define SMEM_F16 (2 * STAGE_B)          // 69632
#define XPITCH_B 272                    // fp16 row: 128 fp16 + 16B pad
#define F16_B    (NTILE_N * XPITCH_B)   // 17408
#define SMEM_DYN (2 * STAGE_B + F16_B)  // 87040

__device__ uint4 a_frag8[8 * 32];       // [class][lane], fp16 G frags

// ---------------------------------------------------------------------------
__device__ __forceinline__ uint32_t s2u(const void* p) {
    uint32_t a;
    asm("{ .reg .u64 t; cvta.to.shared.u64 t, %1; cvt.u32.u64 %0, t; }"
        : "=r"(a) : "l"(p));
    return a;
}
__device__ __forceinline__ uint32_t pack_f16x2(float lo, float hi) {
    uint32_t r;
    asm("cvt.rn.f16x2.f32 %0, %1, %2;" : "=r"(r) : "f"(hi), "f"(lo));
    return r;
}
__device__ __forceinline__ void cp_async16(uint32_t dst, const void* src) {
    asm volatile("cp.async.cg.shared.global [%0], [%1], 16;"
                 :: "r"(dst), "l"(src) : "memory");
}
__device__ __forceinline__ void cp_commit() {
    asm volatile("cp.async.commit_group;" ::: "memory");
}
__device__ __forceinline__ void cp_wait1() {
    asm volatile("cp.async.wait_group 1;" ::: "memory");
}
__device__ __forceinline__ void ldsm_x4(uint32_t& r0, uint32_t& r1,
                                        uint32_t& r2, uint32_t& r3, uint32_t a) {
    asm volatile("ldmatrix.sync.aligned.m8n8.x4.shared.b16 {%0,%1,%2,%3}, [%4];"
                 : "=r"(r0), "=r"(r1), "=r"(r2), "=r"(r3) : "r"(a));
}
__device__ __forceinline__ void mma16816(float* c, const uint4& a,
                                         uint32_t b0, uint32_t b1) {
    asm volatile(
        "mma.sync.aligned.m16n8k16.row.col.f32.f16.f16.f32 "
        "{%0,%1,%2,%3}, {%4,%5,%6,%7}, {%8,%9}, {%0,%1,%2,%3};"
        : "+f"(c[0]), "+f"(c[1]), "+f"(c[2]), "+f"(c[3])
        : "r"(a.x), "r"(a.y), "r"(a.z), "r"(a.w), "r"(b0), "r"(b1));
}

// ---------------------------------------------------------------------------
// Prep: compute g (validated R1), write the 8-class A-fragment table.
// ---------------------------------------------------------------------------
__global__ void prep_kernel(const float* __restrict__ filt) {
    __shared__ float tw_re[CCH], tw_im[CCH];
    __shared__ float inv_re[CCH], inv_im[CCH];
    __shared__ float ft[SCOPE];
    __shared__ float g_s[CCH];
    int t = threadIdx.x;   // 0..255
    if (t < SCOPE) ft[t] = filt[t];
    if (t < CCH) {
        float s, c;
        sincosf(6.283185307179586f * (float)t / 128.0f, &s, &c);
        tw_re[t] = c; tw_im[t] = s;
    }
    __syncthreads();
    if (t < CCH) {
        float fr = 1.0f, fi = 0.0f;
#pragma unroll
        for (int j = 0; j < SCOPE; j++) {
            int p = (115 + j) & 127;
            int idx = (t * p) & 127;
            fr -= ft[j] * tw_re[idx];
            fi += ft[j] * tw_im[idx];
        }
        float d = fr * fr + fi * fi;
        inv_re[t] = fr / d; inv_im[t] = -fi / d;
    }
    __syncthreads();
    if (t < CCH) {
        float acc = 0.0f;
        for (int f = 0; f < CCH; f++) {
            int idx = (f * t) & 127;
            acc += tw_re[idx] * inv_re[f] - tw_im[idx] * inv_im[f];
        }
        g_s[t] = acc * (1.0f / 128.0f);
    }
    __syncthreads();

    {
        int cls  = t >> 5;          // 0..7
        int lane = t & 31;
        int d0 = (16 * cls + (lane >> 2) - 2 * (lane & 3)) & 127;
        uint4 h;
        h.x = pack_f16x2(g_s[d0], g_s[(d0 - 1) & 127]);
        int d1 = (d0 + 8) & 127;
        h.y = pack_f16x2(g_s[d1], g_s[(d1 - 1) & 127]);
        int d2 = (d0 - 8) & 127;
        h.z = pack_f16x2(g_s[d2], g_s[(d2 - 1) & 127]);
        h.w = h.x;
        a_frag8[t] = h;
    }
}

// ---------------------------------------------------------------------------
// Persistent staged GEMM, depth-2 prefetch.
// Tile = 128 out-channels x 64 spatial cols. 8 warps: warp_m = wid&3,
// warp_n = wid>>2.
// ---------------------------------------------------------------------------
__global__ void __launch_bounds__(NTHREADS, 2)
gemm_mma(const float* __restrict__ x, float* __restrict__ y) {
    extern __shared__ char smc[];
    const int tid  = threadIdx.x;
    const int wid  = tid >> 5;
    const int lane = tid & 31;
    const int warp_m = wid & 3;
    const int warp_n = wid >> 2;

    // A fragments: 8 diagonal classes; index (mt - ks)&7 after folding warp_m.
    uint4 areg[8];
#pragma unroll
    for (int i = 0; i < 8; i++)
        areg[i] = a_frag8[(((warp_m * 2) + i) & 7) * 32 + lane];

    const uint32_t smb = s2u(smc);

    // staging-copy constants: thread covers chunks (k, n4)
    // convert-phase constants: thread -> (n-row n0, k-quarter kq)
    const int n0 = tid & 63;
    const int kq = tid >> 6;                 // 0..3
    const int rr = n0 & 31;
    const int nu = ((rr & 6) << 2) | ((rr >> 2) & 6) | (rr & 1);
    const int src_col = (n0 & ~31) + nu;     // permuted staging column

    // ldsm constants (fp16 buf rows = n, 64 rows, pitch 272)
    const uint32_t lm_off = ((lane & 7) + ((lane >> 4) << 3)) * XPITCH_B
                          + ((lane >> 3) & 1) * 16
                          + (uint32_t)warp_n * 32 * XPITCH_B;
    const uint32_t xh_base = smb + SMEM_F16 + lm_off;

    int tile = blockIdx.x;
    if (tile >= NTILES_TOTAL) return;
    const int stride = gridDim.x;

    // ---- prologue: stage tile and tile+stride into S0, S1 ----
    {
        const float* xb = x + (size_t)(tile >> 6) * CCH * HWSZ
                            + (tile & 63) * NTILE_N;
#pragma unroll
        for (int i = 0; i < 8; i++) {
            int c = tid + NTHREADS * i;      // 0..2047 16B chunks
            int k = c >> 4, n4 = c & 15;
            cp_async16(smb + SMEM_S0 + k * SPITCH_B + n4 * 16,
                       xb + (size_t)k * HWSZ + n4 * 4);
        }
        cp_commit();
        const int t1 = tile + stride;
        if (t1 < NTILES_TOTAL) {
            const float* xb1 = x + (size_t)(t1 >> 6) * CCH * HWSZ
                                 + (t1 & 63) * NTILE_N;
#pragma unroll
            for (int i = 0; i < 8; i++) {
                int c = tid + NTHREADS * i;
                int k = c >> 4, n4 = c & 15;
                cp_async16(smb + SMEM_S1 + k * SPITCH_B + n4 * 16,
                           xb1 + (size_t)k * HWSZ + n4 * 4);
            }
        }
        cp_commit();
    }

    int par = 0;
    for (; tile < NTILES_TOTAL; tile += stride, par ^= 1) {
        const uint32_t stage = smb + (par ? SMEM_S1 : SMEM_S0);

        cp_wait1();        // staging(tile) landed; (tile+stride) may still fly
        __syncthreads();   // all threads see it; fp16 buf free

        // ---- convert: staging fp32 [k][n] -> fp16 buf [n][k] (permuted) ----
        {
            const char* sk = smc + (stage - smb) + src_col * 4
                           + (size_t)(kq * 32) * SPITCH_B;
            char* dk = smc + SMEM_F16 + (uint32_t)n0 * XPITCH_B + kq * 64;
#pragma unroll
            for (int ch = 0; ch < 4; ch++) {
                float v[8];
#pragma unroll
                for (int ii = 0; ii < 8; ii++)
                    v[ii] = *reinterpret_cast<const float*>(
                        sk + (size_t)(ch * 8 + ii) * SPITCH_B);
                uint4 hq;
                hq.x = pack_f16x2(v[0], v[1]);
                hq.y = pack_f16x2(v[2], v[3]);
                hq.z = pack_f16x2(v[4], v[5]);
                hq.w = pack_f16x2(v[6], v[7]);
                *reinterpret_cast<uint4*>(dk + ch * 16) = hq;
            }
        }
        __syncthreads();   // fp16 buf ready; staging(tile) reads done

        // ---- stage tile+2*stride into the buffer just drained ----
        {
            const int nxt2 = tile + 2 * stride;
            if (nxt2 < NTILES_TOTAL) {
                const float* xb2 = x + (size_t)(nxt2 >> 6) * CCH * HWSZ
                                     + (nxt2 & 63) * NTILE_N;
#pragma unroll
                for (int i = 0; i < 8; i++) {
                    int c = tid + NTHREADS * i;
                    int k = c >> 4, n4 = c & 15;
                    cp_async16(stage + k * SPITCH_B + n4 * 16,
                               xb2 + (size_t)k * HWSZ + n4 * 4);
                }
            }
            cp_commit();   // commit unconditionally to keep group count in sync
        }

        // ---- mma: 2 mtiles x 4 ntiles, 8 ksteps ----
        float acc[2][4][4];
#pragma unroll
        for (int mt = 0; mt < 2; mt++)
#pragma unroll
            for (int nt = 0; nt < 4; nt++)
#pragma unroll
                for (int r = 0; r < 4; r++) acc[mt][nt][r] = 0.0f;

#pragma unroll
        for (int ks = 0; ks < 8; ks++) {
            const uint32_t kofs = (uint32_t)ks * 32;
#pragma unroll
            for (int p = 0; p < 2; p++) {
                uint32_t b0, b1, b2, b3;
                ldsm_x4(b0, b1, b2, b3, xh_base + p * (16 * XPITCH_B) + kofs);
#pragma unroll
                for (int mt = 0; mt < 2; mt++) {
                    const uint4& a = areg[(mt - ks) & 7];
                    mma16816(acc[mt][2 * p],     a, b0, b1);
                    mma16816(acc[mt][2 * p + 1], a, b2, b3);
                }
            }
        }

        // ---- epilogue: lane holds cols [8q,8q+8) of rows m0, m0+8 ----
        {
            float* yb = y + (size_t)(tile >> 6) * CCH * HWSZ
                          + (tile & 63) * NTILE_N;
            const int q = lane & 3;
#pragma unroll
            for (int mt = 0; mt < 2; mt++) {
                int m0 = warp_m * 32 + mt * 16 + (lane >> 2);
                float* yr0 = yb + (size_t)m0 * HWSZ + warp_n * 32 + 8 * q;
                float* yr8 = yr0 + (size_t)8 * HWSZ;
                *reinterpret_cast<float4*>(yr0) =
                    make_float4(acc[mt][0][0], acc[mt][0][1],
                                acc[mt][1][0], acc[mt][1][1]);
                *reinterpret_cast<float4*>(yr0 + 4) =
                    make_float4(acc[mt][2][0], acc[mt][2][1],
                                acc[mt][3][0], acc[mt][3][1]);
                *reinterpret_cast<float4*>(yr8) =
                    make_float4(acc[mt][0][2], acc[mt][0][3],
                                acc[mt][1][2], acc[mt][1][3]);
                *reinterpret_cast<float4*>(yr8 + 4) =
                    make_float4(acc[mt][2][2], acc[mt][2][3],
                                acc[mt][3][2], acc[mt][3][3]);
            }
        }
    }
}

// ---------------------------------------------------------------------------
extern "C" void kernel_launch(void* const* d_in, const int* in_sizes, int n_in,
                              void* d_out, int out_size) {
    const float* act  = (const float*)d_in[0];
    const float* filt = (const float*)d_in[1];
    if (n_in >= 2 && in_sizes[0] == SCOPE) {
        act  = (const float*)d_in[1];
        filt = (const float*)d_in[0];
    }
    float* out = (float*)d_out;

    prep_kernel<<<1, 256>>>(filt);

    int nsm = 148;
    cudaDeviceGetAttribute(&nsm, cudaDevAttrMultiProcessorCount, 0);
    int grid = 2 * nsm;
    if (grid > NTILES_TOTAL) grid = NTILES_TOTAL;

    cudaFuncSetAttribute(gemm_mma,
                         cudaFuncAttributeMaxDynamicSharedMemorySize, SMEM_DYN);
    gemm_mma<<<grid, NTHREADS, SMEM_DYN>>>(act, out);
}

// round 12
// speedup vs baseline: 1.1230x; 1.1230x over previous
#include <cuda_runtime.h>
#include <cuda_fp16.h>
#include <cstdint>
#include <math.h>

// ConvergedInhibition == circular deconvolution along C=128 channels.
// Y = G @ X, G[r][j] = g[(r-j)&127], g = ifft(1/fft(delta-k)).
// R12: occupancy play. 512-thread CTAs (16 warps, warp tile 32m x 16n),
//      <=64 regs/thread (acc 16 + areg 24 via h.w==h.x), depth-1 cp.async
//      staging (52KB) -> 2 CTAs/SM = 32 warps/SM (2x R11). Single-pass
//      fp16 mma, circulant register A-frags, contiguous-float4 epilogue.

#define CCH     128
#define HWSZ    4096
#define NBATCH  64
#define SCOPE   27
#define NTILE_N 64
#define NTHREADS 512
#define NTILES_TOTAL (NBATCH * (HWSZ / NTILE_N))   // 4096

#define SPITCH_B 272                    // staging row: 64 fp32 + 16B pad
#define STAGE_B  (CCH * SPITCH_B)       // 34816
#define SMEM_F16 STAGE_B
#define XPITCH_B 272                    // fp16 row: 128 fp16 + 16B pad
#define F16_B    (NTILE_N * XPITCH_B)   // 17408
#define SMEM_DYN (STAGE_B + F16_B)      // 52224

__device__ uint32_t af_x[8 * 32];       // [class][lane] fragment words
__device__ uint32_t af_y[8 * 32];
__device__ uint32_t af_z[8 * 32];       // (w == x, not stored)

// ---------------------------------------------------------------------------
__device__ __forceinline__ uint32_t s2u(const void* p) {
    uint32_t a;
    asm("{ .reg .u64 t; cvta.to.shared.u64 t, %1; cvt.u32.u64 %0, t; }"
        : "=r"(a) : "l"(p));
    return a;
}
__device__ __forceinline__ uint32_t pack_f16x2(float lo, float hi) {
    uint32_t r;
    asm("cvt.rn.f16x2.f32 %0, %1, %2;" : "=r"(r) : "f"(hi), "f"(lo));
    return r;
}
__device__ __forceinline__ void cp_async16(uint32_t dst, const void* src) {
    asm volatile("cp.async.cg.shared.global [%0], [%1], 16;"
                 :: "r"(dst), "l"(src) : "memory");
}
__device__ __forceinline__ void cp_commit() {
    asm volatile("cp.async.commit_group;" ::: "memory");
}
__device__ __forceinline__ void cp_wait0() {
    asm volatile("cp.async.wait_group 0;" ::: "memory");
}
__device__ __forceinline__ void ldsm_x4(uint32_t& r0, uint32_t& r1,
                                        uint32_t& r2, uint32_t& r3, uint32_t a) {
    asm volatile("ldmatrix.sync.aligned.m8n8.x4.shared.b16 {%0,%1,%2,%3}, [%4];"
                 : "=r"(r0), "=r"(r1), "=r"(r2), "=r"(r3) : "r"(a));
}
__device__ __forceinline__ void mma16816(float* c, uint32_t ax, uint32_t ay,
                                         uint32_t az, uint32_t b0, uint32_t b1) {
    asm volatile(
        "mma.sync.aligned.m16n8k16.row.col.f32.f16.f16.f32 "
        "{%0,%1,%2,%3}, {%4,%5,%6,%4}, {%7,%8}, {%0,%1,%2,%3};"
        : "+f"(c[0]), "+f"(c[1]), "+f"(c[2]), "+f"(c[3])
        : "r"(ax), "r"(ay), "r"(az), "r"(b0), "r"(b1));
}

// ---------------------------------------------------------------------------
// Prep: compute g (validated R1), write the 8-class A-fragment words.
// Class c: d0 = (16c + (lane>>2) - 2(lane&3)) & 127;
//   x = f16x2(g[d0], g[d0-1]); y: d0+8; z: d0-8; (w == x).
// ---------------------------------------------------------------------------
__global__ void prep_kernel(const float* __restrict__ filt) {
    __shared__ float tw_re[CCH], tw_im[CCH];
    __shared__ float inv_re[CCH], inv_im[CCH];
    __shared__ float ft[SCOPE];
    __shared__ float g_s[CCH];
    int t = threadIdx.x;   // 0..255
    if (t < SCOPE) ft[t] = filt[t];
    if (t < CCH) {
        float s, c;
        sincosf(6.283185307179586f * (float)t / 128.0f, &s, &c);
        tw_re[t] = c; tw_im[t] = s;
    }
    __syncthreads();
    if (t < CCH) {
        float fr = 1.0f, fi = 0.0f;
#pragma unroll
        for (int j = 0; j < SCOPE; j++) {
            int p = (115 + j) & 127;
            int idx = (t * p) & 127;
            fr -= ft[j] * tw_re[idx];
            fi += ft[j] * tw_im[idx];
        }
        float d = fr * fr + fi * fi;
        inv_re[t] = fr / d; inv_im[t] = -fi / d;
    }
    __syncthreads();
    if (t < CCH) {
        float acc = 0.0f;
        for (int f = 0; f < CCH; f++) {
            int idx = (f * t) & 127;
            acc += tw_re[idx] * inv_re[f] - tw_im[idx] * inv_im[f];
        }
        g_s[t] = acc * (1.0f / 128.0f);
    }
    __syncthreads();

    {
        int cls  = t >> 5;          // 0..7
        int lane = t & 31;
        int d0 = (16 * cls + (lane >> 2) - 2 * (lane & 3)) & 127;
        af_x[t] = pack_f16x2(g_s[d0], g_s[(d0 - 1) & 127]);
        int d1 = (d0 + 8) & 127;
        af_y[t] = pack_f16x2(g_s[d1], g_s[(d1 - 1) & 127]);
        int d2 = (d0 - 8) & 127;
        af_z[t] = pack_f16x2(g_s[d2], g_s[(d2 - 1) & 127]);
    }
}

// ---------------------------------------------------------------------------
// Persistent staged GEMM, 512 threads. Tile = 128m x 64n.
// 16 warps: warp_m = wid&3 (32 rows), warp_n = wid>>2 (16 cols).
// Column permutation within 16-col blocks: smem row n holds global col
//   gamma(n) = 4*((n>>1)&3) + 2*((n>>3)&1) + (n&1)
// so lane q's accumulators are {4q..4q+3} per row -> one contiguous float4.
// ---------------------------------------------------------------------------
__global__ void __launch_bounds__(NTHREADS, 2)
gemm_mma(const float* __restrict__ x, float* __restrict__ y) {
    extern __shared__ char smc[];
    const int tid  = threadIdx.x;
    const int wid  = tid >> 5;
    const int lane = tid & 31;
    const int warp_m = wid & 3;
    const int warp_n = wid >> 2;

    // A fragments: 8 diagonal classes, 3 words each (w == x).
    uint32_t ax[8], ay[8], az[8];
#pragma unroll
    for (int i = 0; i < 8; i++) {
        int e = (((warp_m * 2) + i) & 7) * 32 + lane;
        ax[i] = af_x[e]; ay[i] = af_y[e]; az[i] = af_z[e];
    }

    const uint32_t smb = s2u(smc);

    // convert-phase constants: thread -> (n-row n0, k-eighth kq)
    const int n0 = tid & 63;
    const int kq = tid >> 6;                 // 0..7 (16 k's each)
    const int nn = n0 & 15;
    const int gam = 4 * ((nn >> 1) & 3) + 2 * ((nn >> 3) & 1) + (nn & 1);
    const int src_col = (n0 & ~15) + gam;    // permuted staging column

    // ldsm constants (fp16 buf rows = n, 64 rows, pitch 272)
    const uint32_t lm_off = ((lane & 7) + ((lane >> 4) << 3)) * XPITCH_B
                          + ((lane >> 3) & 1) * 16
                          + (uint32_t)warp_n * 16 * XPITCH_B;
    const uint32_t xh_base = smb + SMEM_F16 + lm_off;

    int tile = blockIdx.x;
    if (tile >= NTILES_TOTAL) return;
    const int stride = gridDim.x;

    // ---- prologue: stage tile0 (2048 16B chunks, 4 per thread) ----
    {
        const float* xb = x + (size_t)(tile >> 6) * CCH * HWSZ
                            + (tile & 63) * NTILE_N;
#pragma unroll
        for (int i = 0; i < 4; i++) {
            int c = tid + NTHREADS * i;
            int k = c >> 4, n4 = c & 15;
            cp_async16(smb + k * SPITCH_B + n4 * 16,
                       xb + (size_t)k * HWSZ + n4 * 4);
        }
        cp_commit();
    }

    for (; tile < NTILES_TOTAL; tile += stride) {
        const int nxt = tile + stride;
        const bool hn = nxt < NTILES_TOTAL;

        cp_wait0();
        __syncthreads();   // staging(tile) visible; fp16 buf free

        // ---- convert: staging fp32 [k][n] -> fp16 buf [n][k] (permuted) ----
        {
            const char* sk = smc + src_col * 4 + (size_t)(kq * 16) * SPITCH_B;
            char* dk = smc + SMEM_F16 + (uint32_t)n0 * XPITCH_B + kq * 32;
#pragma unroll
            for (int ch = 0; ch < 2; ch++) {
                float v[8];
#pragma unroll
                for (int ii = 0; ii < 8; ii++)
                    v[ii] = *reinterpret_cast<const float*>(
                        sk + (size_t)(ch * 8 + ii) * SPITCH_B);
                uint4 hq;
                hq.x = pack_f16x2(v[0], v[1]);
                hq.y = pack_f16x2(v[2], v[3]);
                hq.z = pack_f16x2(v[4], v[5]);
                hq.w = pack_f16x2(v[6], v[7]);
                *reinterpret_cast<uint4*>(dk + ch * 16) = hq;
            }
        }
        __syncthreads();   // fp16 buf ready; staging reads done

        // ---- stage next tile (covered by mma + epilogue) ----
        if (hn) {
            const float* xbn = x + (size_t)(nxt >> 6) * CCH * HWSZ
                                 + (nxt & 63) * NTILE_N;
#pragma unroll
            for (int i = 0; i < 4; i++) {
                int c = tid + NTHREADS * i;
                int k = c >> 4, n4 = c & 15;
                cp_async16(smb + k * SPITCH_B + n4 * 16,
                           xbn + (size_t)k * HWSZ + n4 * 4);
            }
        }
        cp_commit();

        // ---- mma: 2 mtiles x 2 ntiles, 8 ksteps, 1 ldsm.x4 per kstep ----
        float acc[2][2][4];
#pragma unroll
        for (int mt = 0; mt < 2; mt++)
#pragma unroll
            for (int nt = 0; nt < 2; nt++)
#pragma unroll
                for (int r = 0; r < 4; r++) acc[mt][nt][r] = 0.0f;

#pragma unroll
        for (int ks = 0; ks < 8; ks++) {
            uint32_t b0, b1, b2, b3;
            ldsm_x4(b0, b1, b2, b3, xh_base + (uint32_t)ks * 32);
#pragma unroll
            for (int mt = 0; mt < 2; mt++) {
                const int ai = (mt - ks) & 7;
                mma16816(acc[mt][0], ax[ai], ay[ai], az[ai], b0, b1);
                mma16816(acc[mt][1], ax[ai], ay[ai], az[ai], b2, b3);
            }
        }

        // ---- epilogue: lane q -> cols [4q,4q+4) of rows m0, m0+8 ----
        {
            float* yb = y + (size_t)(tile >> 6) * CCH * HWSZ
                          + (tile & 63) * NTILE_N + warp_n * 16
                          + 4 * (lane & 3);
#pragma unroll
            for (int mt = 0; mt < 2; mt++) {
                int m0 = warp_m * 32 + mt * 16 + (lane >> 2);
                *reinterpret_cast<float4*>(yb + (size_t)m0 * HWSZ) =
                    make_float4(acc[mt][0][0], acc[mt][0][1],
                                acc[mt][1][0], acc[mt][1][1]);
                *reinterpret_cast<float4*>(yb + (size_t)(m0 + 8) * HWSZ) =
                    make_float4(acc[mt][0][2], acc[mt][0][3],
                                acc[mt][1][2], acc[mt][1][3]);
            }
        }
    }
}

// ---------------------------------------------------------------------------
extern "C" void kernel_launch(void* const* d_in, const int* in_sizes, int n_in,
                              void* d_out, int out_size) {
    const float* act  = (const float*)d_in[0];
    const float* filt = (const float*)d_in[1];
    if (n_in >= 2 && in_sizes[0] == SCOPE) {
        act  = (const float*)d_in[1];
        filt = (const float*)d_in[0];
    }
    float* out = (float*)d_out;

    prep_kernel<<<1, 256>>>(filt);

    int nsm = 148;
    cudaDeviceGetAttribute(&nsm, cudaDevAttrMultiProcessorCount, 0);
    int grid = 2 * nsm;
    if (grid > NTILES_TOTAL) grid = NTILES_TOTAL;

    cudaFuncSetAttribute(gemm_mma,
                         cudaFuncAttributeMaxDynamicSharedMemorySize, SMEM_DYN);
    gemm_mma<<<grid, NTHREADS, SMEM_DYN>>>(act, out);
}

// round 13
// speedup vs baseline: 1.1237x; 1.0006x over previous
#include <cuda_runtime.h>
#include <cuda_fp16.h>
#include <cstdint>
#include <math.h>

// ConvergedInhibition == circular deconvolution along C=128 channels.
// Y = G @ X, G[r][j] = g[(r-j)&127], g = ifft(1/fft(delta-k)).
// R13: R12 + reordered double-double pipeline: per tile,
//        issue cp(t+2) -> mma(t)+epi -> wait cp(t+1) -> convert(t+1)
//      so each cp gets ~2 tile-bodies of cover. 512-thread CTAs,
//      <=64 regs, 2 CTAs/SM. Single-pass fp16 mma, circulant register
//      A-frags, contiguous-float4 epilogue.

#define CCH     128
#define HWSZ    4096
#define NBATCH  64
#define SCOPE   27
#define NTILE_N 64
#define NTHREADS 512
#define NTILES_TOTAL (NBATCH * (HWSZ / NTILE_N))   // 4096

#define SPITCH_B 272                    // staging row: 64 fp32 + 16B pad
#define STAGE_B  (CCH * SPITCH_B)       // 34816
#define XPITCH_B 272                    // fp16 row: 128 fp16 + 16B pad
#define F16_B    (NTILE_N * XPITCH_B)   // 17408
#define SMEM_S0  0
#define SMEM_S1  STAGE_B
#define SMEM_F0  (2 * STAGE_B)          // 69632
#define SMEM_F1  (2 * STAGE_B + F16_B)  // 87040
#define SMEM_DYN (2 * STAGE_B + 2 * F16_B)  // 104448

__device__ uint32_t af_x[8 * 32];       // [class][lane] fragment words
__device__ uint32_t af_y[8 * 32];
__device__ uint32_t af_z[8 * 32];       // (w == x, not stored)

// ---------------------------------------------------------------------------
__device__ __forceinline__ uint32_t s2u(const void* p) {
    uint32_t a;
    asm("{ .reg .u64 t; cvta.to.shared.u64 t, %1; cvt.u32.u64 %0, t; }"
        : "=r"(a) : "l"(p));
    return a;
}
__device__ __forceinline__ uint32_t pack_f16x2(float lo, float hi) {
    uint32_t r;
    asm("cvt.rn.f16x2.f32 %0, %1, %2;" : "=r"(r) : "f"(hi), "f"(lo));
    return r;
}
__device__ __forceinline__ void cp_async16(uint32_t dst, const void* src) {
    asm volatile("cp.async.cg.shared.global [%0], [%1], 16;"
                 :: "r"(dst), "l"(src) : "memory");
}
__device__ __forceinline__ void cp_commit() {
    asm volatile("cp.async.commit_group;" ::: "memory");
}
__device__ __forceinline__ void cp_wait0() {
    asm volatile("cp.async.wait_group 0;" ::: "memory");
}
__device__ __forceinline__ void cp_wait1() {
    asm volatile("cp.async.wait_group 1;" ::: "memory");
}
__device__ __forceinline__ void ldsm_x4(uint32_t& r0, uint32_t& r1,
                                        uint32_t& r2, uint32_t& r3, uint32_t a) {
    asm volatile("ldmatrix.sync.aligned.m8n8.x4.shared.b16 {%0,%1,%2,%3}, [%4];"
                 : "=r"(r0), "=r"(r1), "=r"(r2), "=r"(r3) : "r"(a));
}
__device__ __forceinline__ void mma16816(float* c, uint32_t ax, uint32_t ay,
                                         uint32_t az, uint32_t b0, uint32_t b1) {
    asm volatile(
        "mma.sync.aligned.m16n8k16.row.col.f32.f16.f16.f32 "
        "{%0,%1,%2,%3}, {%4,%5,%6,%4}, {%7,%8}, {%0,%1,%2,%3};"
        : "+f"(c[0]), "+f"(c[1]), "+f"(c[2]), "+f"(c[3])
        : "r"(ax), "r"(ay), "r"(az), "r"(b0), "r"(b1));
}

// ---------------------------------------------------------------------------
// Prep: compute g (validated R1), write the 8-class A-fragment words.
// ---------------------------------------------------------------------------
__global__ void prep_kernel(const float* __restrict__ filt) {
    __shared__ float tw_re[CCH], tw_im[CCH];
    __shared__ float inv_re[CCH], inv_im[CCH];
    __shared__ float ft[SCOPE];
    __shared__ float g_s[CCH];
    int t = threadIdx.x;   // 0..255
    if (t < SCOPE) ft[t] = filt[t];
    if (t < CCH) {
        float s, c;
        sincosf(6.283185307179586f * (float)t / 128.0f, &s, &c);
        tw_re[t] = c; tw_im[t] = s;
    }
    __syncthreads();
    if (t < CCH) {
        float fr = 1.0f, fi = 0.0f;
#pragma unroll
        for (int j = 0; j < SCOPE; j++) {
            int p = (115 + j) & 127;
            int idx = (t * p) & 127;
            fr -= ft[j] * tw_re[idx];
            fi += ft[j] * tw_im[idx];
        }
        float d = fr * fr + fi * fi;
        inv_re[t] = fr / d; inv_im[t] = -fi / d;
    }
    __syncthreads();
    if (t < CCH) {
        float acc = 0.0f;
        for (int f = 0; f < CCH; f++) {
            int idx = (f * t) & 127;
            acc += tw_re[idx] * inv_re[f] - tw_im[idx] * inv_im[f];
        }
        g_s[t] = acc * (1.0f / 128.0f);
    }
    __syncthreads();

    {
        int cls  = t >> 5;          // 0..7
        int lane = t & 31;
        int d0 = (16 * cls + (lane >> 2) - 2 * (lane & 3)) & 127;
        af_x[t] = pack_f16x2(g_s[d0], g_s[(d0 - 1) & 127]);
        int d1 = (d0 + 8) & 127;
        af_y[t] = pack_f16x2(g_s[d1], g_s[(d1 - 1) & 127]);
        int d2 = (d0 - 8) & 127;
        af_z[t] = pack_f16x2(g_s[d2], g_s[(d2 - 1) & 127]);
    }
}

// ---------------------------------------------------------------------------
// Persistent staged GEMM, 512 threads, reordered pipeline.
// Tile = 128m x 64n. 16 warps: warp_m = wid&3 (32 rows), warp_n = wid>>2.
// ---------------------------------------------------------------------------
__global__ void __launch_bounds__(NTHREADS, 2)
gemm_mma(const float* __restrict__ x, float* __restrict__ y) {
    extern __shared__ char smc[];
    const int tid  = threadIdx.x;
    const int wid  = tid >> 5;
    const int lane = tid & 31;
    const int warp_m = wid & 3;
    const int warp_n = wid >> 2;

    // A fragments: 8 diagonal classes, 3 words each (w == x).
    uint32_t ax[8], ay[8], az[8];
#pragma unroll
    for (int i = 0; i < 8; i++) {
        int e = (((warp_m * 2) + i) & 7) * 32 + lane;
        ax[i] = af_x[e]; ay[i] = af_y[e]; az[i] = af_z[e];
    }

    const uint32_t smb = s2u(smc);

    // copy constants (thread -> 4 chunks of (k, n4))
    // convert constants: thread -> (n-row n0, k-eighth kq)
    const int n0 = tid & 63;
    const int kq = tid >> 6;                 // 0..7 (16 k's each)
    const int nn = n0 & 15;
    const int gam = 4 * ((nn >> 1) & 3) + 2 * ((nn >> 3) & 1) + (nn & 1);
    const int src_col = (n0 & ~15) + gam;    // permuted staging column

    // ldsm constants (fp16 buf rows = n, 64 rows, pitch 272)
    const uint32_t lm_off = ((lane & 7) + ((lane >> 4) << 3)) * XPITCH_B
                          + ((lane >> 3) & 1) * 16
                          + (uint32_t)warp_n * 16 * XPITCH_B;

    int tile = blockIdx.x;
    if (tile >= NTILES_TOTAL) return;
    const int stride = gridDim.x;

    // ---- copy lambda-ish macro: stage tile tt into staging base sb ----
#define STAGE_TILE(tt, sb)                                                   \
    do {                                                                     \
        const float* xb_ = x + (size_t)((tt) >> 6) * CCH * HWSZ              \
                             + ((tt) & 63) * NTILE_N;                        \
        _Pragma("unroll")                                                    \
        for (int i_ = 0; i_ < 4; i_++) {                                     \
            int c_ = tid + NTHREADS * i_;                                    \
            int k_ = c_ >> 4, n4_ = c_ & 15;                                 \
            cp_async16((sb) + k_ * SPITCH_B + n4_ * 16,                      \
                       xb_ + (size_t)k_ * HWSZ + n4_ * 4);                   \
        }                                                                    \
    } while (0)

#define CONVERT_TILE(soff, foff)                                             \
    do {                                                                     \
        const char* sk_ = smc + (soff) + src_col * 4                         \
                        + (size_t)(kq * 16) * SPITCH_B;                      \
        char* dk_ = smc + (foff) + (uint32_t)n0 * XPITCH_B + kq * 32;        \
        _Pragma("unroll")                                                    \
        for (int ch_ = 0; ch_ < 2; ch_++) {                                  \
            float v_[8];                                                     \
            _Pragma("unroll")                                                \
            for (int ii_ = 0; ii_ < 8; ii_++)                                \
                v_[ii_] = *reinterpret_cast<const float*>(                   \
                    sk_ + (size_t)(ch_ * 8 + ii_) * SPITCH_B);               \
            uint4 hq_;                                                       \
            hq_.x = pack_f16x2(v_[0], v_[1]);                                \
            hq_.y = pack_f16x2(v_[2], v_[3]);                                \
            hq_.z = pack_f16x2(v_[4], v_[5]);                                \
            hq_.w = pack_f16x2(v_[6], v_[7]);                                \
            *reinterpret_cast<uint4*>(dk_ + ch_ * 16) = hq_;                 \
        }                                                                    \
    } while (0)

    // ---- prologue ----
    STAGE_TILE(tile, smb + SMEM_S0);
    cp_commit();                       // group: t0
    cp_wait0();
    __syncthreads();
    CONVERT_TILE(SMEM_S0, SMEM_F0);    // f16[0] = tile0
    __syncthreads();                   // stg0 reads done; f16[0] visible
    {
        const int t1 = tile + stride;
        if (t1 < NTILES_TOTAL) STAGE_TILE(t1, smb + SMEM_S1);
        cp_commit();                   // group: t1
    }

    int par = 0;
    // invariant at loop top: f16[par] = tile t (all warps see it);
    // stg[par^1] carries cp(t+1) (committed, possibly in flight);
    // stg[par] free (its convert reads completed before last barrier).
    for (; tile < NTILES_TOTAL; tile += stride, par ^= 1) {
        // 1. issue cp(t+2) into the free staging buffer
        {
            const int n2 = tile + 2 * stride;
            if (n2 < NTILES_TOTAL)
                STAGE_TILE(n2, smb + (par ? SMEM_S1 : SMEM_S0));
            cp_commit();
        }

        // 2. mma(t) from f16[par] + epilogue (covers cp(t+1), cp(t+2))
        {
            const uint32_t xh_base = smb + (par ? SMEM_F1 : SMEM_F0) + lm_off;
            float acc[2][2][4];
#pragma unroll
            for (int mt = 0; mt < 2; mt++)
#pragma unroll
                for (int nt = 0; nt < 2; nt++)
#pragma unroll
                    for (int r = 0; r < 4; r++) acc[mt][nt][r] = 0.0f;

#pragma unroll
            for (int ks = 0; ks < 8; ks++) {
                uint32_t b0, b1, b2, b3;
                ldsm_x4(b0, b1, b2, b3, xh_base + (uint32_t)ks * 32);
#pragma unroll
                for (int mt = 0; mt < 2; mt++) {
                    const int ai = (mt - ks) & 7;
                    mma16816(acc[mt][0], ax[ai], ay[ai], az[ai], b0, b1);
                    mma16816(acc[mt][1], ax[ai], ay[ai], az[ai], b2, b3);
                }
            }

            float* yb = y + (size_t)(tile >> 6) * CCH * HWSZ
                          + (tile & 63) * NTILE_N + warp_n * 16
                          + 4 * (lane & 3);
#pragma unroll
            for (int mt = 0; mt < 2; mt++) {
                int m0 = warp_m * 32 + mt * 16 + (lane >> 2);
                *reinterpret_cast<float4*>(yb + (size_t)m0 * HWSZ) =
                    make_float4(acc[mt][0][0], acc[mt][0][1],
                                acc[mt][1][0], acc[mt][1][1]);
                *reinterpret_cast<float4*>(yb + (size_t)(m0 + 8) * HWSZ) =
                    make_float4(acc[mt][0][2], acc[mt][0][3],
                                acc[mt][1][2], acc[mt][1][3]);
            }
        }

        // 3. cp(t+1) must be landed; make visible to all warps
        cp_wait1();
        __syncthreads();

        // 4. convert(t+1): stg[par^1] -> f16[par^1]
        if (tile + stride < NTILES_TOTAL) {
            if (par) CONVERT_TILE(SMEM_S0, SMEM_F0);
            else     CONVERT_TILE(SMEM_S1, SMEM_F1);
        }
        __syncthreads();   // f16[par^1] ready; stg[par^1] reads done
    }
#undef STAGE_TILE
#undef CONVERT_TILE
}

// ---------------------------------------------------------------------------
extern "C" void kernel_launch(void* const* d_in, const int* in_sizes, int n_in,
                              void* d_out, int out_size) {
    const float* act  = (const float*)d_in[0];
    const float* filt = (const float*)d_in[1];
    if (n_in >= 2 && in_sizes[0] == SCOPE) {
        act  = (const float*)d_in[1];
        filt = (const float*)d_in[0];
    }
    float* out = (float*)d_out;

    prep_kernel<<<1, 256>>>(filt);

    int nsm = 148;
    cudaDeviceGetAttribute(&nsm, cudaDevAttrMultiProcessorCount, 0);
    int grid = 2 * nsm;
    if (grid > NTILES_TOTAL) grid = NTILES_TOTAL;

    cudaFuncSetAttribute(gemm_mma,
                         cudaFuncAttributeMaxDynamicSharedMemorySize, SMEM_DYN);
    gemm_mma<<<grid, NTHREADS, SMEM_DYN>>>(act, out);
}

// round 14
// speedup vs baseline: 1.1409x; 1.0152x over previous
#include <cuda_runtime.h>
#include <cuda_fp16.h>
#include <cstdint>
#include <math.h>

// ConvergedInhibition == circular deconvolution along C=128 channels.
// Y = G @ X, G[r][j] = g[(r-j)&127], g = ifft(1/fft(delta-k)).
// R14: R13 with prep FOLDED INTO the gemm kernel (single graph node).
//      Each CTA computes g via direct DFT at startup, hidden behind the
//      tile-0 cp.async staging burst; A-fragments built from smem g_s.
//      512-thread CTAs, <=64 regs, 2 CTAs/SM, depth-2 reordered pipeline,
//      single-pass fp16 mma, circulant register A-frags, float4 epilogue.

#define CCH     128
#define HWSZ    4096
#define NBATCH  64
#define SCOPE   27
#define NTILE_N 64
#define NTHREADS 512
#define NTILES_TOTAL (NBATCH * (HWSZ / NTILE_N))   // 4096

#define SPITCH_B 272                    // staging row: 64 fp32 + 16B pad
#define STAGE_B  (CCH * SPITCH_B)       // 34816
#define XPITCH_B 272                    // fp16 row: 128 fp16 + 16B pad
#define F16_B    (NTILE_N * XPITCH_B)   // 17408
#define SMEM_S0  0
#define SMEM_S1  STAGE_B
#define SMEM_F0  (2 * STAGE_B)          // 69632
#define SMEM_F1  (2 * STAGE_B + F16_B)  // 87040
#define SMEM_DYN (2 * STAGE_B + 2 * F16_B)  // 104448

// ---------------------------------------------------------------------------
__device__ __forceinline__ uint32_t s2u(const void* p) {
    uint32_t a;
    asm("{ .reg .u64 t; cvta.to.shared.u64 t, %1; cvt.u32.u64 %0, t; }"
        : "=r"(a) : "l"(p));
    return a;
}
__device__ __forceinline__ uint32_t pack_f16x2(float lo, float hi) {
    uint32_t r;
    asm("cvt.rn.f16x2.f32 %0, %1, %2;" : "=r"(r) : "f"(hi), "f"(lo));
    return r;
}
__device__ __forceinline__ void cp_async16(uint32_t dst, const void* src) {
    asm volatile("cp.async.cg.shared.global [%0], [%1], 16;"
                 :: "r"(dst), "l"(src) : "memory");
}
__device__ __forceinline__ void cp_commit() {
    asm volatile("cp.async.commit_group;" ::: "memory");
}
__device__ __forceinline__ void cp_wait0() {
    asm volatile("cp.async.wait_group 0;" ::: "memory");
}
__device__ __forceinline__ void cp_wait1() {
    asm volatile("cp.async.wait_group 1;" ::: "memory");
}
__device__ __forceinline__ void ldsm_x4(uint32_t& r0, uint32_t& r1,
                                        uint32_t& r2, uint32_t& r3, uint32_t a) {
    asm volatile("ldmatrix.sync.aligned.m8n8.x4.shared.b16 {%0,%1,%2,%3}, [%4];"
                 : "=r"(r0), "=r"(r1), "=r"(r2), "=r"(r3) : "r"(a));
}
__device__ __forceinline__ void mma16816(float* c, uint32_t ax, uint32_t ay,
                                         uint32_t az, uint32_t b0, uint32_t b1) {
    asm volatile(
        "mma.sync.aligned.m16n8k16.row.col.f32.f16.f16.f32 "
        "{%0,%1,%2,%3}, {%4,%5,%6,%4}, {%7,%8}, {%0,%1,%2,%3};"
        : "+f"(c[0]), "+f"(c[1]), "+f"(c[2]), "+f"(c[3])
        : "r"(ax), "r"(ay), "r"(az), "r"(b0), "r"(b1));
}

// ---------------------------------------------------------------------------
// Persistent staged GEMM, 512 threads, in-kernel prep.
// Tile = 128m x 64n. 16 warps: warp_m = wid&3 (32 rows), warp_n = wid>>2.
// ---------------------------------------------------------------------------
__global__ void __launch_bounds__(NTHREADS, 2)
gemm_mma(const float* __restrict__ x, const float* __restrict__ filt,
         float* __restrict__ y) {
    extern __shared__ char smc[];
    __shared__ float tw_re[CCH], tw_im[CCH];
    __shared__ float inv_re[CCH], inv_im[CCH];
    __shared__ float ft[SCOPE];
    __shared__ float g_s[CCH];

    const int tid  = threadIdx.x;
    const int wid  = tid >> 5;
    const int lane = tid & 31;
    const int warp_m = wid & 3;
    const int warp_n = wid >> 2;

    const uint32_t smb = s2u(smc);

    int tile = blockIdx.x;
    if (tile >= NTILES_TOTAL) return;
    const int stride = gridDim.x;

#define STAGE_TILE(tt, sb)                                                   \
    do {                                                                     \
        const float* xb_ = x + (size_t)((tt) >> 6) * CCH * HWSZ              \
                             + ((tt) & 63) * NTILE_N;                        \
        _Pragma("unroll")                                                    \
        for (int i_ = 0; i_ < 4; i_++) {                                     \
            int c_ = tid + NTHREADS * i_;                                    \
            int k_ = c_ >> 4, n4_ = c_ & 15;                                 \
            cp_async16((sb) + k_ * SPITCH_B + n4_ * 16,                      \
                       xb_ + (size_t)k_ * HWSZ + n4_ * 4);                   \
        }                                                                    \
    } while (0)

    // ---- stage tile0 FIRST: its DRAM latency covers the g computation ----
    STAGE_TILE(tile, smb + SMEM_S0);
    cp_commit();                       // group: t0

    // ---- in-CTA prep: g = real(ifft(1/fft(delta - k_rolled))) ----
    if (tid < SCOPE) ft[tid] = filt[tid];
    if (tid < CCH) {
        float s, c;
        sincosf(6.283185307179586f * (float)tid / 128.0f, &s, &c);
        tw_re[tid] = c; tw_im[tid] = s;
    }
    __syncthreads();
    if (tid < CCH) {
        float fr = 1.0f, fi = 0.0f;
#pragma unroll
        for (int j = 0; j < SCOPE; j++) {
            int p = (115 + j) & 127;
            int idx = (tid * p) & 127;
            fr -= ft[j] * tw_re[idx];
            fi += ft[j] * tw_im[idx];
        }
        float d = fr * fr + fi * fi;
        inv_re[tid] = fr / d; inv_im[tid] = -fi / d;
    }
    __syncthreads();
    if (tid < CCH) {
        float acc = 0.0f;
        for (int f = 0; f < CCH; f++) {
            int idx = (f * tid) & 127;
            acc += tw_re[idx] * inv_re[f] - tw_im[idx] * inv_im[f];
        }
        g_s[tid] = acc * (1.0f / 128.0f);
    }
    __syncthreads();

    // ---- A fragments from g_s: 8 diagonal classes, 3 words (w == x) ----
    uint32_t ax[8], ay[8], az[8];
#pragma unroll
    for (int i = 0; i < 8; i++) {
        int cls = ((warp_m * 2) + i) & 7;
        int d0 = (16 * cls + (lane >> 2) - 2 * (lane & 3)) & 127;
        ax[i] = pack_f16x2(g_s[d0], g_s[(d0 - 1) & 127]);
        int d1 = (d0 + 8) & 127;
        ay[i] = pack_f16x2(g_s[d1], g_s[(d1 - 1) & 127]);
        int d2 = (d0 - 8) & 127;
        az[i] = pack_f16x2(g_s[d2], g_s[(d2 - 1) & 127]);
    }

    // convert constants: thread -> (n-row n0, k-eighth kq)
    const int n0 = tid & 63;
    const int kq = tid >> 6;                 // 0..7 (16 k's each)
    const int nn = n0 & 15;
    const int gam = 4 * ((nn >> 1) & 3) + 2 * ((nn >> 3) & 1) + (nn & 1);
    const int src_col = (n0 & ~15) + gam;    // permuted staging column

    // ldsm constants (fp16 buf rows = n, 64 rows, pitch 272)
    const uint32_t lm_off = ((lane & 7) + ((lane >> 4) << 3)) * XPITCH_B
                          + ((lane >> 3) & 1) * 16
                          + (uint32_t)warp_n * 16 * XPITCH_B;

#define CONVERT_TILE(soff, foff)                                             \
    do {                                                                     \
        const char* sk_ = smc + (soff) + src_col * 4                         \
                        + (size_t)(kq * 16) * SPITCH_B;                      \
        char* dk_ = smc + (foff) + (uint32_t)n0 * XPITCH_B + kq * 32;        \
        _Pragma("unroll")                                                    \
        for (int ch_ = 0; ch_ < 2; ch_++) {                                  \
            float v_[8];                                                     \
            _Pragma("unroll")                                                \
            for (int ii_ = 0; ii_ < 8; ii_++)                                \
                v_[ii_] = *reinterpret_cast<const float*>(                   \
                    sk_ + (size_t)(ch_ * 8 + ii_) * SPITCH_B);               \
            uint4 hq_;                                                       \
            hq_.x = pack_f16x2(v_[0], v_[1]);                                \
            hq_.y = pack_f16x2(v_[2], v_[3]);                                \
            hq_.z = pack_f16x2(v_[4], v_[5]);                                \
            hq_.w = pack_f16x2(v_[6], v_[7]);                                \
            *reinterpret_cast<uint4*>(dk_ + ch_ * 16) = hq_;                 \
        }                                                                    \
    } while (0)

    // ---- prologue (continues): convert tile0, stage tile1 ----
    cp_wait0();
    __syncthreads();
    CONVERT_TILE(SMEM_S0, SMEM_F0);    // f16[0] = tile0
    __syncthreads();                   // stg0 reads done; f16[0] visible
    {
        const int t1 = tile + stride;
        if (t1 < NTILES_TOTAL) STAGE_TILE(t1, smb + SMEM_S1);
        cp_commit();                   // group: t1
    }

    int par = 0;
    // invariant at loop top: f16[par] = tile t (all warps see it);
    // stg[par^1] carries cp(t+1); stg[par] free.
    for (; tile < NTILES_TOTAL; tile += stride, par ^= 1) {
        // 1. issue cp(t+2) into the free staging buffer
        {
            const int n2 = tile + 2 * stride;
            if (n2 < NTILES_TOTAL)
                STAGE_TILE(n2, smb + (par ? SMEM_S1 : SMEM_S0));
            cp_commit();
        }

        // 2. mma(t) from f16[par] + epilogue (covers cp(t+1), cp(t+2))
        {
            const uint32_t xh_base = smb + (par ? SMEM_F1 : SMEM_F0) + lm_off;
            float acc[2][2][4];
#pragma unroll
            for (int mt = 0; mt < 2; mt++)
#pragma unroll
                for (int nt = 0; nt < 2; nt++)
#pragma unroll
                    for (int r = 0; r < 4; r++) acc[mt][nt][r] = 0.0f;

#pragma unroll
            for (int ks = 0; ks < 8; ks++) {
                uint32_t b0, b1, b2, b3;
                ldsm_x4(b0, b1, b2, b3, xh_base + (uint32_t)ks * 32);
#pragma unroll
                for (int mt = 0; mt < 2; mt++) {
                    const int ai = (mt - ks) & 7;
                    mma16816(acc[mt][0], ax[ai], ay[ai], az[ai], b0, b1);
                    mma16816(acc[mt][1], ax[ai], ay[ai], az[ai], b2, b3);
                }
            }

            float* yb = y + (size_t)(tile >> 6) * CCH * HWSZ
                          + (tile & 63) * NTILE_N + warp_n * 16
                          + 4 * (lane & 3);
#pragma unroll
            for (int mt = 0; mt < 2; mt++) {
                int m0 = warp_m * 32 + mt * 16 + (lane >> 2);
                *reinterpret_cast<float4*>(yb + (size_t)m0 * HWSZ) =
                    make_float4(acc[mt][0][0], acc[mt][0][1],
                                acc[mt][1][0], acc[mt][1][1]);
                *reinterpret_cast<float4*>(yb + (size_t)(m0 + 8) * HWSZ) =
                    make_float4(acc[mt][0][2], acc[mt][0][3],
                                acc[mt][1][2], acc[mt][1][3]);
            }
        }

        // 3. cp(t+1) landed; make visible to all warps
        cp_wait1();
        __syncthreads();

        // 4. convert(t+1): stg[par^1] -> f16[par^1]
        if (tile + stride < NTILES_TOTAL) {
            if (par) CONVERT_TILE(SMEM_S0, SMEM_F0);
            else     CONVERT_TILE(SMEM_S1, SMEM_F1);
        }
        __syncthreads();   // f16[par^1] ready; stg[par^1] reads done
    }
#undef STAGE_TILE
#undef CONVERT_TILE
}

// ---------------------------------------------------------------------------
extern "C" void kernel_launch(void* const* d_in, const int* in_sizes, int n_in,
                              void* d_out, int out_size) {
    const float* act  = (const float*)d_in[0];
    const float* filt = (const float*)d_in[1];
    if (n_in >= 2 && in_sizes[0] == SCOPE) {
        act  = (const float*)d_in[1];
        filt = (const float*)d_in[0];
    }
    float* out = (float*)d_out;

    int nsm = 148;
    cudaDeviceGetAttribute(&nsm, cudaDevAttrMultiProcessorCount, 0);
    int grid = 2 * nsm;
    if (grid > NTILES_TOTAL) grid = NTILES_TOTAL;

    cudaFuncSetAttribute(gemm_mma,
                         cudaFuncAttributeMaxDynamicSharedMemorySize, SMEM_DYN);
    gemm_mma<<<grid, NTHREADS, SMEM_DYN>>>(act, filt, out);
}